// round 1
// baseline (speedup 1.0000x reference)
#include <cuda_runtime.h>

#define CIN   128
#define COUT  64
#define HIN   64
#define WIN   64
#define BATCH 8
#define HO    129
#define WO    129

// Repacked weights: [c][kh][kw][o]  (o fastest -> coalesced shared-tile loads)
__device__ float g_wT[CIN * 9 * COUT];

__global__ void repack_w_kernel(const float* __restrict__ w) {
    int idx = blockIdx.x * blockDim.x + threadIdx.x;   // over CIN*9*COUT
    if (idx < CIN * 9 * COUT) {
        int o = idx & 63;
        int p = idx >> 6;                              // c*9 + kh*3 + kw
        g_wT[idx] = w[o * (CIN * 9) + p];
    }
}

__device__ __forceinline__ unsigned long long pack2(float lo, float hi) {
    unsigned long long r;
    asm("mov.b64 %0, {%1, %2};" : "=l"(r) : "f"(lo), "f"(hi));
    return r;
}
__device__ __forceinline__ void fma2(unsigned long long& d, unsigned long long a, unsigned long long b) {
    asm("fma.rn.f32x2 %0, %1, %2, %0;" : "+l"(d) : "l"(a), "l"(b));
}
__device__ __forceinline__ float2 unpack2(unsigned long long v) {
    float lo, hi;
    asm("mov.b64 {%0, %1}, %2;" : "=f"(lo), "=f"(hi) : "l"(v));
    return make_float2(lo, hi);
}

// One parity class: outputs i = 2a+PI, j = 2b'+PJ.
//   PI==0: kh taps {0,2} -> input rows {a-1, a}   (shared rows rg+v+dr, dr in {0,1})
//   PI==1: kh tap  {1}   -> input row  {a}        (dr = 1, shared tile holds halo row)
// Same for columns with PJ/kw.
template<int PI, int PJ>
__device__ __forceinline__ void convt_body(
    const float* __restrict__ x, float* __restrict__ y,
    float (&Xs)[8][17][18], float (&Ws)[8][4][COUT], int bb)
{
    constexpr int NH = (PI == 0) ? 2 : 1;
    constexpr int NW = (PJ == 0) ? 2 : 1;
    constexpr int NT = NH * NW;
    constexpr int NA = (PI == 0) ? 65 : 64;   // a-range
    constexpr int NB = (PJ == 0) ? 65 : 64;   // b'-range
    constexpr int TA = 16, TB = 16;
    constexpr int KC = 8;

    const int a0 = blockIdx.y * TA;
    const int b0 = blockIdx.x * TB;
    if (a0 >= NA || b0 >= NB) return;         // uniform per block -> safe early exit

    const int tx = threadIdx.x;
    const int og = tx >> 5;                   // warp id -> o base og*8 (broadcast W in warp)
    const int pg = tx & 31;
    const int cb = pg & 15;                   // column within tile (16 cols across warp)
    const int rg = (pg >> 4) * 8;             // row-group base (0 or 8), 8 rows per thread

    unsigned long long acc[4][8];             // [o-pair][row v]
#pragma unroll
    for (int k2 = 0; k2 < 4; k2++)
#pragma unroll
        for (int v = 0; v < 8; v++) acc[k2][v] = 0ULL;

    const float* xb = x + (size_t)bb * CIN * HIN * WIN;

    for (int c0 = 0; c0 < CIN; c0 += KC) {
        // ---- load X tile with 1-halo (rows a0-1.., cols b0-1..), zero-padded OOB
        for (int idx = tx; idx < KC * 17 * 17; idx += 256) {
            int cc  = idx / (17 * 17);
            int rem = idx - cc * (17 * 17);
            int rr  = rem / 17;
            int cl  = rem - rr * 17;
            int gr  = a0 - 1 + rr;
            int gc  = b0 - 1 + cl;
            float v = 0.f;
            if ((unsigned)gr < HIN && (unsigned)gc < WIN)
                v = xb[((c0 + cc) * HIN + gr) * WIN + gc];
            Xs[cc][rr][cl] = v;
        }
        // ---- load W tile from repacked layout (o-contiguous -> coalesced)
        for (int idx = tx; idx < KC * NT * COUT; idx += 256) {
            int cc  = idx / (NT * COUT);
            int rem = idx - cc * (NT * COUT);
            int t   = rem >> 6;
            int o   = rem & 63;
            int th  = t / NW, tw = t % NW;
            int kh  = (PI == 0) ? th * 2 : 1;
            int kw  = (PJ == 0) ? tw * 2 : 1;
            Ws[cc][t][o] = g_wT[((c0 + cc) * 9 + kh * 3 + kw) * COUT + o];
        }
        __syncthreads();

#pragma unroll 4
        for (int cc = 0; cc < KC; cc++) {
#pragma unroll
            for (int t = 0; t < NT; t++) {
                const int th = t / NW, tw = t % NW;
                const int dr = (PI == 0) ? th : 1;
                const int dc = (PJ == 0) ? tw : 1;
                unsigned long long xd[8];
#pragma unroll
                for (int v = 0; v < 8; v++) {
                    float xv = Xs[cc][rg + v + dr][cb + dc];
                    xd[v] = pack2(xv, xv);
                }
                const unsigned long long* wrow =
                    reinterpret_cast<const unsigned long long*>(&Ws[cc][t][og * 8]);
#pragma unroll
                for (int k2 = 0; k2 < 4; k2++) {
                    unsigned long long w2 = wrow[k2];
#pragma unroll
                    for (int v = 0; v < 8; v++)
                        fma2(acc[k2][v], w2, xd[v]);
                }
            }
        }
        __syncthreads();
    }

    // ---- store: j stride-2 within class (16 consecutive cols per half-warp)
    const int obase = og * 8;
    const int col   = b0 + cb;
    if (col < NB) {
        const int j = 2 * col + PJ;
#pragma unroll
        for (int v = 0; v < 8; v++) {
            int a = a0 + rg + v;
            if (a < NA) {
                int i = 2 * a + PI;
#pragma unroll
                for (int k2 = 0; k2 < 4; k2++) {
                    float2 p = unpack2(acc[k2][v]);
                    int o = obase + 2 * k2;
                    y[(((size_t)bb * COUT + o) * HO + i) * WO + j]       = p.x;
                    y[(((size_t)bb * COUT + o + 1) * HO + i) * WO + j]   = p.y;
                }
            }
        }
    }
}

__global__ void __launch_bounds__(256)
convt_all_kernel(const float* __restrict__ x, float* __restrict__ y)
{
    __shared__ __align__(16) float Xs[8][17][18];
    __shared__ __align__(16) float Ws[8][4][COUT];
    const int cls = blockIdx.z & 3;
    const int bb  = blockIdx.z >> 2;
    switch (cls) {
        case 0: convt_body<0,0>(x, y, Xs, Ws, bb); break;
        case 1: convt_body<0,1>(x, y, Xs, Ws, bb); break;
        case 2: convt_body<1,0>(x, y, Xs, Ws, bb); break;
        case 3: convt_body<1,1>(x, y, Xs, Ws, bb); break;
    }
}

extern "C" void kernel_launch(void* const* d_in, const int* in_sizes, int n_in,
                              void* d_out, int out_size) {
    const float* x = (const float*)d_in[0];
    const float* w = (const float*)d_in[1];
    // defensive: identify weight by its element count
    if (n_in >= 2 && in_sizes[0] == COUT * CIN * 9) {
        const float* t = x; x = w; w = t;
    }
    float* y = (float*)d_out;

    repack_w_kernel<<<(CIN * 9 * COUT + 255) / 256, 256>>>(w);
    // grid.z = batch*4 classes; x/y tile grids sized for the largest class (65x65),
    // smaller classes early-exit their extra tiles.
    convt_all_kernel<<<dim3(5, 5, BATCH * 4), 256>>>(x, y);
}

// round 11
// speedup vs baseline: 1.0497x; 1.0497x over previous
#include <cuda_runtime.h>

#define CIN   128
#define COUT  64
#define HIN   64
#define WIN   64
#define BATCH 8
#define HO    129
#define WO    129

// Repacked weights: [c][kh][kw][o]  (o fastest -> coalesced shared-tile loads)
__device__ float g_wT[CIN * 9 * COUT];

__global__ void repack_w_kernel(const float* __restrict__ w) {
    int idx = blockIdx.x * blockDim.x + threadIdx.x;   // over CIN*9*COUT
    if (idx < CIN * 9 * COUT) {
        int o = idx & 63;
        int p = idx >> 6;                              // c*9 + kh*3 + kw
        g_wT[idx] = w[o * (CIN * 9) + p];
    }
}

__device__ __forceinline__ unsigned long long pack2(float lo, float hi) {
    unsigned long long r;
    asm("mov.b64 %0, {%1, %2};" : "=l"(r) : "f"(lo), "f"(hi));
    return r;
}
__device__ __forceinline__ void fma2(unsigned long long& d, unsigned long long a, unsigned long long b) {
    asm("fma.rn.f32x2 %0, %1, %2, %0;" : "+l"(d) : "l"(a), "l"(b));
}
__device__ __forceinline__ float2 unpack2(unsigned long long v) {
    float lo, hi;
    asm("mov.b64 {%0, %1}, %2;" : "=f"(lo), "=f"(hi) : "l"(v));
    return make_float2(lo, hi);
}

// One parity class: outputs i = 2a+PI, j = 2b'+PJ.
// Rows are FLATTENED over (batch, a): flat f in [0, BATCH*NAR). A 16-row tile
// may span a batch boundary; the overlapping halo row there is zero from both
// sides, so a single shared tile remains consistent (see R2 notes).
// Column tiles cover b' in [0,64) only; column b'=64 (j=128) of the NB=65
// classes is produced by strip_kernel (it only uses the kw=0 tap).
template<int PI, int PJ, int NAR, int NB>
__device__ __forceinline__ void convt_body(
    const float* __restrict__ x, float* __restrict__ y,
    float (&Xs)[8][17][18], float (&Ws)[8][4][COUT], int (&rowbase)[17],
    int tr, int tc)
{
    constexpr int NH = (PI == 0) ? 2 : 1;
    constexpr int NW = (PJ == 0) ? 2 : 1;
    constexpr int NT = NH * NW;
    constexpr int FTOT = BATCH * NAR;   // flat row count
    constexpr int KC = 8;

    const int f0 = tr * 16;
    const int b0 = tc * 16;
    const int tx = threadIdx.x;
    const int og = tx >> 5;                   // warp id -> o base og*8 (broadcast W in warp)
    const int pg = tx & 31;
    const int cb = pg & 15;                   // column within tile (16 cols across warp)
    const int rg = (pg >> 4) * 8;             // row-group base (0 or 8), 8 rows per thread

    // ---- per-block row table: global x element offset of each shared row, -1 if pad
    if (tx < 17) {
        int p   = (PI == 0) ? (f0 + tx) : (f0 + tx - 1);
        int b   = p / NAR;                    // p >= -1; guarded below
        int ain = p - b * NAR - ((PI == 0) ? 1 : 0);
        bool ok = (p >= 0) && (b < BATCH) && (ain >= 0) && (ain < HIN);
        rowbase[tx] = ok ? ((b * CIN + 0) * HIN * WIN + ain * WIN) : -1;
    }
    __syncthreads();

    unsigned long long acc[4][8];             // [o-pair][row v]
#pragma unroll
    for (int k2 = 0; k2 < 4; k2++)
#pragma unroll
        for (int v = 0; v < 8; v++) acc[k2][v] = 0ULL;

    for (int c0 = 0; c0 < CIN; c0 += KC) {
        // ---- load X tile (17 rows x 17 cols, zero-padded)
        for (int idx = tx; idx < KC * 17 * 17; idx += 256) {
            int cc  = idx / (17 * 17);
            int rem = idx - cc * (17 * 17);
            int rr  = rem / 17;
            int cl  = rem - rr * 17;
            int rb  = rowbase[rr];
            int gc  = b0 - 1 + cl;
            float v = 0.f;
            if (rb >= 0 && (unsigned)gc < WIN)
                v = x[rb + (c0 + cc) * (HIN * WIN) + gc];
            Xs[cc][rr][cl] = v;
        }
        // ---- load W tile from repacked layout (o-contiguous -> coalesced)
        for (int idx = tx; idx < KC * NT * COUT; idx += 256) {
            int cc  = idx / (NT * COUT);
            int rem = idx - cc * (NT * COUT);
            int t   = rem >> 6;
            int o   = rem & 63;
            int th  = t / NW, tw = t % NW;
            int kh  = (PI == 0) ? th * 2 : 1;
            int kw  = (PJ == 0) ? tw * 2 : 1;
            Ws[cc][t][o] = g_wT[((c0 + cc) * 9 + kh * 3 + kw) * COUT + o];
        }
        __syncthreads();

#pragma unroll 4
        for (int cc = 0; cc < KC; cc++) {
#pragma unroll
            for (int t = 0; t < NT; t++) {
                const int th = t / NW, tw = t % NW;
                const int dr = (PI == 0) ? th : 1;
                const int dc = (PJ == 0) ? tw : 1;
                unsigned long long xd[8];
#pragma unroll
                for (int v = 0; v < 8; v++) {
                    float xv = Xs[cc][rg + v + dr][cb + dc];
                    xd[v] = pack2(xv, xv);
                }
                const unsigned long long* wrow =
                    reinterpret_cast<const unsigned long long*>(&Ws[cc][t][og * 8]);
#pragma unroll
                for (int k2 = 0; k2 < 4; k2++) {
                    unsigned long long w2 = wrow[k2];
#pragma unroll
                    for (int v = 0; v < 8; v++)
                        fma2(acc[k2][v], w2, xd[v]);
                }
            }
        }
        __syncthreads();
    }

    // ---- store: decode flat row -> (batch, a); j stride-2 within class
    const int obase = og * 8;
    const int col   = b0 + cb;
    if (col < NB) {
        const int j = 2 * col + PJ;
#pragma unroll
        for (int v = 0; v < 8; v++) {
            int f = f0 + rg + v;
            if (f < FTOT) {
                int bb = f / NAR;
                int a  = f - bb * NAR;
                int i  = 2 * a + PI;
#pragma unroll
                for (int k2 = 0; k2 < 4; k2++) {
                    float2 p = unpack2(acc[k2][v]);
                    int o = obase + 2 * k2;
                    y[(((size_t)bb * COUT + o) * HO + i) * WO + j]     = p.x;
                    y[(((size_t)bb * COUT + o + 1) * HO + i) * WO + j] = p.y;
                }
            }
        }
    }
}

// Boundary strip: y[b, o, i, 128] for the two PJ=0 classes.
// j=128 admits only kw=0 (kw=2 -> input col 64 OOB), against input col 63.
//   even i=2a : kh=0 -> row a-1 (pad if a==0), kh=2 -> row a (invalid if a==64)
//   odd  i=2a+1: kh=1 -> row a
__global__ void __launch_bounds__(64)
strip_kernel(const float* __restrict__ x, float* __restrict__ y)
{
    __shared__ float xs0[CIN], xs1[CIN];
    const int bi = blockIdx.x;           // 0 .. BATCH*HO-1
    const int bb = bi / HO;
    const int i  = bi - bb * HO;
    const int o  = threadIdx.x;          // 0..63
    const int a  = i >> 1;
    const bool odd = (i & 1) != 0;
    const int r0 = odd ? a : a - 1;      // kh=1 (odd) / kh=0 (even)
    const int r1 = a;                    // kh=2 (even only)

    for (int c = o; c < CIN; c += 64) {
        const float* xb = x + ((size_t)bb * CIN + c) * (HIN * WIN) + (WIN - 1);
        xs0[c] = ((unsigned)r0 < HIN) ? xb[r0 * WIN] : 0.f;
        xs1[c] = (!odd && (unsigned)r1 < HIN) ? xb[r1 * WIN] : 0.f;
    }
    __syncthreads();

    float acc = 0.f;
    if (odd) {
        for (int c = 0; c < CIN; c++)
            acc += g_wT[(c * 9 + 3) * COUT + o] * xs0[c];       // kh=1, kw=0
    } else {
        float acc2 = 0.f;
        for (int c = 0; c < CIN; c++) {
            acc  += g_wT[(c * 9 + 0) * COUT + o] * xs0[c];      // kh=0, kw=0
            acc2 += g_wT[(c * 9 + 6) * COUT + o] * xs1[c];      // kh=2, kw=0
        }
        acc += acc2;
    }
    y[(((size_t)bb * COUT + o) * HO + i) * WO + (WO - 1)] = acc;
}

// Exact per-class grids over b' in [0,64) (4 col tiles each), heavy classes first:
//   class0 (0,0): 33 row-tiles x 4 = 132   [  0,132)
//   class1 (0,1): 33 x 4           = 132   [132,264)
//   class2 (1,0): 32 x 4           = 128   [264,392)
//   class3 (1,1): 32 x 4           = 128   [392,520)
#define NBLK 520

__global__ void __launch_bounds__(256)
convt_all_kernel(const float* __restrict__ x, float* __restrict__ y)
{
    __shared__ __align__(16) float Xs[8][17][18];
    __shared__ __align__(16) float Ws[8][4][COUT];
    __shared__ int rowbase[17];
    const int bid = blockIdx.x;
    if (bid < 132) {
        convt_body<0,0,65,65>(x, y, Xs, Ws, rowbase, bid / 4, bid % 4);
    } else if (bid < 264) {
        int t = bid - 132;
        convt_body<0,1,65,64>(x, y, Xs, Ws, rowbase, t / 4, t % 4);
    } else if (bid < 392) {
        int t = bid - 264;
        convt_body<1,0,64,65>(x, y, Xs, Ws, rowbase, t / 4, t % 4);
    } else {
        int t = bid - 392;
        convt_body<1,1,64,64>(x, y, Xs, Ws, rowbase, t / 4, t % 4);
    }
}

extern "C" void kernel_launch(void* const* d_in, const int* in_sizes, int n_in,
                              void* d_out, int out_size) {
    const float* x = (const float*)d_in[0];
    const float* w = (const float*)d_in[1];
    // defensive: identify weight by its element count
    if (n_in >= 2 && in_sizes[0] == COUT * CIN * 9) {
        const float* t = x; x = w; w = t;
    }
    float* y = (float*)d_out;

    repack_w_kernel<<<(CIN * 9 * COUT + 255) / 256, 256>>>(w);
    convt_all_kernel<<<NBLK, 256>>>(x, y);
    strip_kernel<<<BATCH * HO, 64>>>(x, y);
}